// round 13
// baseline (speedup 1.0000x reference)
#include <cuda_runtime.h>
#include <cstdint>
#include <math.h>
#include <mma.h>

using namespace nvcuda;

typedef unsigned long long u64;

// Problem constants
#define B_ 2
#define S_ 2048
#define D_ 2048
#define H_ 16
#define HD_ 128
#define RD_ 64
#define L_ 512
#define QDIM (HD_ + RD_)      // 192
#define KVDIM (2*HD_ + RD_)   // 320
#define MROWS (B_ * S_)       // 4096

// Scratch (device globals; no cudaMalloc allowed)
__device__ float g_ckv[MROWS * L_];
__device__ float g_cq [MROWS * L_];
__device__ float g_kv [MROWS * H_ * KVDIM];
__device__ float g_q  [MROWS * H_ * QDIM];
__device__ float g_ctx[MROWS * H_ * HD_];
// tf32-rounded operand copies
__device__ float g_xt [MROWS * D_];
__device__ float g_w1t[D_ * L_];
__device__ float g_w2t[L_ * H_ * KVDIM];
__device__ float g_w3t[D_ * L_];
__device__ float g_w4t[L_ * H_ * QDIM];
__device__ float g_w5t[H_ * HD_ * D_];
// RoPE tables: [S_][32]
__device__ float g_cost[S_ * 32];
__device__ float g_sint[S_ * 32];

// ----------------------------------------------------------------------------
// Packed fp32 (f32x2) helpers — FFMA2 path, exact IEEE fp32 per lane.
// ----------------------------------------------------------------------------
__device__ __forceinline__ u64 pack2(float lo, float hi) {
    u64 r;
    asm("mov.b64 %0, {%1, %2};" : "=l"(r) : "r"(__float_as_uint(lo)), "r"(__float_as_uint(hi)));
    return r;
}
__device__ __forceinline__ u64 dup2(float v) {
    u64 r;
    asm("mov.b64 %0, {%1, %1};" : "=l"(r) : "r"(__float_as_uint(v)));
    return r;
}
__device__ __forceinline__ void unpack2(u64 v, float& lo, float& hi) {
    unsigned a, b;
    asm("mov.b64 {%0, %1}, %2;" : "=r"(a), "=r"(b) : "l"(v));
    lo = __uint_as_float(a); hi = __uint_as_float(b);
}
__device__ __forceinline__ void ffma2(u64& d, u64 a, u64 b) {
    asm("fma.rn.f32x2 %0, %1, %2, %0;" : "+l"(d) : "l"(a), "l"(b));
}
__device__ __forceinline__ void fmul2(u64& d, u64 a) {
    asm("mul.rn.f32x2 %0, %0, %1;" : "+l"(d) : "l"(a));
}

// ----------------------------------------------------------------------------
// Prep kernel: all 6 tf32 conversions + RoPE cos/sin table, one launch.
// ----------------------------------------------------------------------------
__device__ __forceinline__ float4 cvt4(float4 v) {
    v.x = wmma::__float_to_tf32(v.x);
    v.y = wmma::__float_to_tf32(v.y);
    v.z = wmma::__float_to_tf32(v.z);
    v.w = wmma::__float_to_tf32(v.w);
    return v;
}

__global__ void __launch_bounds__(256) prep_kernel(
    const float4* __restrict__ x,  const float4* __restrict__ w1,
    const float4* __restrict__ w2, const float4* __restrict__ w3,
    const float4* __restrict__ w4, const float4* __restrict__ w5)
{
    int idx = blockIdx.x * 256 + threadIdx.x;

    if (idx < S_ * 32) {
        int s = idx >> 5, i = idx & 31;
        const float inv_freq = __expf(-(float)i * (9.210340371976184f / 32.0f));
        const float freq = (float)s * inv_freq;
        g_cost[idx] = cosf(freq);
        g_sint[idx] = sinf(freq);
    }

    if (idx < 2097152) {
        ((float4*)g_xt)[idx] = cvt4(x[idx]);
    } else if (idx < 2359296) {
        int j = idx - 2097152; ((float4*)g_w1t)[j] = cvt4(w1[j]);
    } else if (idx < 3014656) {
        int j = idx - 2359296; ((float4*)g_w2t)[j] = cvt4(w2[j]);
    } else if (idx < 3276800) {
        int j = idx - 3014656; ((float4*)g_w3t)[j] = cvt4(w3[j]);
    } else if (idx < 3670016) {
        int j = idx - 3276800; ((float4*)g_w4t)[j] = cvt4(w4[j]);
    } else if (idx < 4718592) {
        int j = idx - 3670016; ((float4*)g_w5t)[j] = cvt4(w5[j]);
    }
}

// ----------------------------------------------------------------------------
// cp.async helpers
// ----------------------------------------------------------------------------
__device__ __forceinline__ void cp16(float* dst, const float* src) {
    unsigned int s = (unsigned int)__cvta_generic_to_shared(dst);
    asm volatile("cp.async.cg.shared.global [%0], [%1], 16;\n" :: "r"(s), "l"(src));
}
#define CP_COMMIT() asm volatile("cp.async.commit_group;\n" ::: "memory")
#define CP_WAIT1()  asm volatile("cp.async.wait_group 1;\n" ::: "memory")

// ----------------------------------------------------------------------------
// TF32 tensor-core GEMM body (R8-proven), shared by 3 wrapper kernels.
// ----------------------------------------------------------------------------
#define AP 36
#define BP 132
#define STAGES 3
#define A_STG (128 * AP)
#define B_STG (32 * BP)
#define GEMM_SMEM (STAGES * (A_STG + B_STG) * (int)sizeof(float))

__device__ __forceinline__ void tgemm_body(
    const float* __restrict__ A, const float* __restrict__ Bm,
    float* __restrict__ C, int N, int K, int roundC, int bRow, int bCol)
{
    extern __shared__ float sm_g[];
    float* As = sm_g;
    float* Bs = sm_g + STAGES * A_STG;

    const int tid = threadIdx.x;
    const int w   = tid >> 5;
    const int wm  = w & 1;
    const int wn  = w >> 1;

    wmma::fragment<wmma::accumulator, 16, 16, 8, float> c[4][4];
#pragma unroll
    for (int i = 0; i < 4; i++)
#pragma unroll
        for (int j = 0; j < 4; j++) wmma::fill_fragment(c[i][j], 0.f);

    const int ktiles = K >> 5;

    auto load_tile = [&](int buf, int kt) {
        float* as = As + buf * A_STG;
        float* bs = Bs + buf * B_STG;
        const float* Ag = A + (size_t)bRow * K + kt * 32;
        const float* Bg = Bm + (size_t)(kt * 32) * N + bCol;
#pragma unroll
        for (int p = 0; p < 8; p++) {
            int idx = p * 128 + tid;
            int r  = idx >> 3, c4  = idx & 7;
            cp16(&as[r * AP + c4 * 4], Ag + (size_t)r * K + c4 * 4);
            int rb = idx >> 5, cb4 = idx & 31;
            cp16(&bs[rb * BP + cb4 * 4], Bg + (size_t)rb * N + cb4 * 4);
        }
    };

    load_tile(0, 0); CP_COMMIT();
    load_tile(1, 1); CP_COMMIT();

    for (int i = 0; i < ktiles; i++) {
        CP_WAIT1();
        __syncthreads();
        if (i + 2 < ktiles) load_tile((i + 2) % STAGES, i + 2);
        CP_COMMIT();

        const float* as = As + (i % STAGES) * A_STG;
        const float* bs = Bs + (i % STAGES) * B_STG;
#pragma unroll
        for (int ks = 0; ks < 32; ks += 8) {
            wmma::fragment<wmma::matrix_a, 16, 16, 8, wmma::precision::tf32, wmma::row_major> a[4];
            wmma::fragment<wmma::matrix_b, 16, 16, 8, wmma::precision::tf32, wmma::row_major> b[4];
#pragma unroll
            for (int ii = 0; ii < 4; ii++)
                wmma::load_matrix_sync(a[ii], &as[(wm * 64 + ii * 16) * AP + ks], AP);
#pragma unroll
            for (int j = 0; j < 4; j++)
                wmma::load_matrix_sync(b[j], &bs[ks * BP + wn * 64 + j * 16], BP);
#pragma unroll
            for (int ii = 0; ii < 4; ii++)
#pragma unroll
                for (int j = 0; j < 4; j++)
                    wmma::mma_sync(c[ii][j], a[ii], b[j], c[ii][j]);
        }
    }

    if (roundC) {
#pragma unroll
        for (int i = 0; i < 4; i++)
#pragma unroll
            for (int j = 0; j < 4; j++)
#pragma unroll
                for (int t = 0; t < c[i][j].num_elements; t++)
                    c[i][j].x[t] = wmma::__float_to_tf32(c[i][j].x[t]);
    }

#pragma unroll
    for (int i = 0; i < 4; i++)
#pragma unroll
        for (int j = 0; j < 4; j++) {
            size_t row = bRow + wm * 64 + i * 16;
            size_t col = bCol + wn * 64 + j * 16;
            wmma::store_matrix_sync(C + row * N + col, c[i][j], N, wmma::mem_row_major);
        }
}

__global__ void __launch_bounds__(128, 2) gemm_down_kernel()
{
    int bx = blockIdx.x;
    if (bx < 4) tgemm_body(g_xt, g_w1t, g_ckv, L_, D_, 1, blockIdx.y * 128, bx * 128);
    else        tgemm_body(g_xt, g_w3t, g_cq,  L_, D_, 1, blockIdx.y * 128, (bx - 4) * 128);
}

__global__ void __launch_bounds__(128, 2) gemm_up_kernel()
{
    int bx = blockIdx.x;
    if (bx < 40) tgemm_body(g_ckv, g_w2t, g_kv, H_ * KVDIM, L_, 0, blockIdx.y * 128, bx * 128);
    else         tgemm_body(g_cq,  g_w4t, g_q,  H_ * QDIM,  L_, 0, blockIdx.y * 128, (bx - 40) * 128);
}

__global__ void __launch_bounds__(128, 2) gemm_out_kernel(float* __restrict__ out)
{
    tgemm_body(g_ctx, g_w5t, out, D_, D_, 0, blockIdx.y * 128, blockIdx.x * 128);
}

// ----------------------------------------------------------------------------
// Causal flash attention v5: fp32 numerics via packed FFMA2 (f32x2).
// 64x128 score tile, 128 threads, 8x8 micro-tiles for both QK^T and PV.
// RoPE fused into Q/K fills (tables). Serial __expf softmax (proven).
// ----------------------------------------------------------------------------
#define TQ 64
#define TK 128
#define QP 68     // sQt pitch (rows)
#define KP 132    // sKt pitch (128 kcols + 4)
#define VP 132
#define SP 132
// sQt 192*68 + sKt 64*132 + sV 128*132 + sS 64*132 + stats 192
#define ATTN_SMEM ((192*QP + 64*KP + TK*VP + TQ*SP + 192) * (int)sizeof(float))

__global__ void __launch_bounds__(128) attn_kernel()
{
    extern __shared__ float sm[];
    float* sQt  = sm;                   // [192][QP]  Q^T (roped)
    float* sKt  = sQt + 192 * QP;       // [64][KP]   K^T chunk (64 dims x 128 kcols)
    float* sV   = sKt + 64 * KP;        // [128][VP]
    float* sS   = sV  + TK * VP;        // [64][SP]
    float* mRow = sS  + TQ * SP;
    float* lRow = mRow + 64;
    float* aRow = lRow + 64;

    const int qt  = blockIdx.x;         // 0..31
    const int h   = blockIdx.y;
    const int b   = blockIdx.z;
    const int qs  = qt * TQ;
    const int tid = threadIdx.x;        // 0..127
    const int ty  = tid >> 4;           // 0..7  -> 8 q-rows
    const int tx  = tid & 15;           // 0..15 -> 8 k-cols / 8 v-cols
    const int r0  = ty * 8;
    const int c0  = tx * 8;

    // Q^T fill, dims 0..127 (no rope)
    for (int idx = tid; idx < TQ * 128; idx += 128) {
        int r = idx >> 7, k = idx & 127;
        sQt[k * QP + r] = g_q[((size_t)(b * S_ + qs + r) * H_ + h) * QDIM + k];
    }
    // Q^T fill, dims 128..191 with RoPE
    for (int idx = tid; idx < TQ * 32; idx += 128) {
        int r = idx >> 5, i = idx & 31;
        size_t base = ((size_t)(b * S_ + qs + r) * H_ + h) * QDIM;
        float x1 = g_q[base + 128 + i];
        float x2 = g_q[base + 160 + i];
        float c  = g_cost[(qs + r) * 32 + i];
        float sn = g_sint[(qs + r) * 32 + i];
        sQt[(128 + i) * QP + r] = x1 * c - x2 * sn;
        sQt[(160 + i) * QP + r] = x2 * c + x1 * sn;
    }
    if (tid < TQ) { mRow[tid] = -INFINITY; lRow[tid] = 0.f; }

    // PV accumulator: 8 rows x 8 vcols packed as [8][4] f32x2
    u64 acc2[8][4];
#pragma unroll
    for (int i = 0; i < 8; i++)
#pragma unroll
        for (int j = 0; j < 4; j++) acc2[i][j] = 0ull;

    const float scale = 0.07216878364870323f;  // 1/sqrt(192)
    const int nkt = (qt >> 1) + 1;              // k-tiles of width 128

    for (int kt = 0; kt < nkt; kt++) {
        const int ks = kt * TK;
        __syncthreads();  // previous iteration done with sS/sV/sKt

        // V tile [128][128] (float4)
        for (int idx4 = tid; idx4 < TK * (HD_ / 4); idx4 += 128) {
            int c = idx4 >> 5, j4 = idx4 & 31;
            float4 v = *(const float4*)(g_kv + ((size_t)(b * S_ + ks + c) * H_ + h) * KVDIM + QDIM + j4 * 4);
            *(float4*)&sV[c * VP + j4 * 4] = v;
        }

        // Scores: 64x128 over 192 dims in 3 chunks of 64; packed f32x2
        u64 s2[8][4];
#pragma unroll
        for (int i = 0; i < 8; i++)
#pragma unroll
            for (int j = 0; j < 4; j++) s2[i][j] = 0ull;

        for (int dc = 0; dc < 3; dc++) {
            if (dc > 0) __syncthreads();   // protect sKt overwrite
            {
                const int cb = tid >> 5;   // 0..3 kcol base
                const int d  = tid & 31;   // dim within 32
                if (dc < 2) {
#pragma unroll 4
                    for (int rr = 0; rr < 32; rr++) {
                        int kc = cb + rr * 4;
                        size_t base = ((size_t)(b * S_ + ks + kc) * H_ + h) * KVDIM + dc * 64;
                        sKt[d        * KP + kc] = g_kv[base + d];
                        sKt[(32 + d) * KP + kc] = g_kv[base + 32 + d];
                    }
                } else {
#pragma unroll 4
                    for (int rr = 0; rr < 32; rr++) {
                        int kc = cb + rr * 4;
                        size_t base = ((size_t)(b * S_ + ks + kc) * H_ + h) * KVDIM;
                        float x1 = g_kv[base + 128 + d];
                        float x2 = g_kv[base + 160 + d];
                        float cc = g_cost[(ks + kc) * 32 + d];
                        float sn = g_sint[(ks + kc) * 32 + d];
                        sKt[d        * KP + kc] = x1 * cc - x2 * sn;
                        sKt[(32 + d) * KP + kc] = x2 * cc + x1 * sn;
                    }
                }
            }
            __syncthreads();
#pragma unroll 4
            for (int k = 0; k < 64; k++) {
                const int kk = dc * 64 + k;
                float4 qa0 = *(const float4*)&sQt[kk * QP + r0];
                float4 qa1 = *(const float4*)&sQt[kk * QP + r0 + 4];
                float4 kb0 = *(const float4*)&sKt[k * KP + c0];
                float4 kb1 = *(const float4*)&sKt[k * KP + c0 + 4];
                u64 bp0 = pack2(kb0.x, kb0.y);
                u64 bp1 = pack2(kb0.z, kb0.w);
                u64 bp2 = pack2(kb1.x, kb1.y);
                u64 bp3 = pack2(kb1.z, kb1.w);
                float qv[8] = {qa0.x, qa0.y, qa0.z, qa0.w, qa1.x, qa1.y, qa1.z, qa1.w};
#pragma unroll
                for (int i = 0; i < 8; i++) {
                    u64 ad = dup2(qv[i]);
                    ffma2(s2[i][0], ad, bp0);
                    ffma2(s2[i][1], ad, bp1);
                    ffma2(s2[i][2], ad, bp2);
                    ffma2(s2[i][3], ad, bp3);
                }
            }
        }

        // Unpack, scale, mask, store scores
        {
            const bool diag = (ks + TK > qs);
#pragma unroll
            for (int i = 0; i < 8; i++) {
                const int gr = qs + r0 + i;
                float v[8];
#pragma unroll
                for (int j = 0; j < 4; j++) unpack2(s2[i][j], v[2*j], v[2*j+1]);
                float o[8];
#pragma unroll
                for (int j = 0; j < 8; j++) {
                    int kc = ks + c0 + j;
                    o[j] = (diag && kc > gr) ? -1e30f : v[j] * scale;
                }
                *(float4*)&sS[(r0 + i) * SP + c0]     = make_float4(o[0], o[1], o[2], o[3]);
                *(float4*)&sS[(r0 + i) * SP + c0 + 4] = make_float4(o[4], o[5], o[6], o[7]);
            }
        }
        __syncthreads();

        // Online softmax row update (serial per row — proven fastest config)
        if (tid < TQ) {
            const int r = tid;
            float mold = mRow[r];
            float mx = mold;
#pragma unroll 8
            for (int c = 0; c < TK; c++) mx = fmaxf(mx, sS[r * SP + c]);
            float a = __expf(mold - mx);
            float sum = 0.f;
#pragma unroll 8
            for (int c = 0; c < TK; c++) {
                float p = __expf(sS[r * SP + c] - mx);
                sS[r * SP + c] = p;
                sum += p;
            }
            lRow[r] = lRow[r] * a + sum;
            mRow[r] = mx;
            aRow[r] = a;
        }
        __syncthreads();

        // acc2 = acc2*alpha + P @ V   (packed f32x2; 8 rows x 8 vcols)
        {
#pragma unroll
            for (int i = 0; i < 8; i++) {
                u64 ad = dup2(aRow[r0 + i]);
#pragma unroll
                for (int j = 0; j < 4; j++) fmul2(acc2[i][j], ad);
            }
#pragma unroll 2
            for (int c = 0; c < TK; c++) {
                float4 v0 = *(const float4*)&sV[c * VP + c0];
                float4 v1 = *(const float4*)&sV[c * VP + c0 + 4];
                u64 vp0 = pack2(v0.x, v0.y);
                u64 vp1 = pack2(v0.z, v0.w);
                u64 vp2 = pack2(v1.x, v1.y);
                u64 vp3 = pack2(v1.z, v1.w);
#pragma unroll
                for (int i = 0; i < 8; i++) {
                    u64 pd = dup2(sS[(r0 + i) * SP + c]);
                    ffma2(acc2[i][0], pd, vp0);
                    ffma2(acc2[i][1], pd, vp1);
                    ffma2(acc2[i][2], pd, vp2);
                    ffma2(acc2[i][3], pd, vp3);
                }
            }
        }
    }

    // Final normalize + store (tf32-rounded: feeds tf32 output GEMM)
#pragma unroll
    for (int i = 0; i < 8; i++) {
        const float invl = 1.0f / lRow[r0 + i];
        size_t ob = ((size_t)(b * S_ + qs + r0 + i) * H_ + h) * HD_ + c0;
        float v[8];
#pragma unroll
        for (int j = 0; j < 4; j++) unpack2(acc2[i][j], v[2*j], v[2*j+1]);
        float o[8];
#pragma unroll
        for (int j = 0; j < 8; j++) o[j] = wmma::__float_to_tf32(v[j] * invl);
        *(float4*)(g_ctx + ob)     = make_float4(o[0], o[1], o[2], o[3]);
        *(float4*)(g_ctx + ob + 4) = make_float4(o[4], o[5], o[6], o[7]);
    }
}

// ----------------------------------------------------------------------------
// Launch: 5 kernels; attn at app-launch index 3 (ncu capture slot).
// Inputs (metadata order): x, mask, w_kv_down, w_kv_up, w_q_down, w_q_up, w_o
// ----------------------------------------------------------------------------
extern "C" void kernel_launch(void* const* d_in, const int* in_sizes, int n_in,
                              void* d_out, int out_size)
{
    (void)in_sizes; (void)n_in; (void)out_size;
    const float* x         = (const float*)d_in[0];
    const float* w_kv_down = (const float*)d_in[2];
    const float* w_kv_up   = (const float*)d_in[3];
    const float* w_q_down  = (const float*)d_in[4];
    const float* w_q_up    = (const float*)d_in[5];
    const float* w_o       = (const float*)d_in[6];
    float* out = (float*)d_out;

    cudaFuncSetAttribute(gemm_down_kernel, cudaFuncAttributeMaxDynamicSharedMemorySize, GEMM_SMEM);
    cudaFuncSetAttribute(gemm_up_kernel,   cudaFuncAttributeMaxDynamicSharedMemorySize, GEMM_SMEM);
    cudaFuncSetAttribute(gemm_out_kernel,  cudaFuncAttributeMaxDynamicSharedMemorySize, GEMM_SMEM);
    cudaFuncSetAttribute(attn_kernel,      cudaFuncAttributeMaxDynamicSharedMemorySize, ATTN_SMEM);

    // 0: prep (tf32 conversions + rope tables)
    prep_kernel<<<18432, 256>>>((const float4*)x, (const float4*)w_kv_down,
                                (const float4*)w_kv_up, (const float4*)w_q_down,
                                (const float4*)w_q_up, (const float4*)w_o);
    // 1: fused down projections
    gemm_down_kernel<<<dim3(8, 32), 128, GEMM_SMEM>>>();
    // 2: fused up projections
    gemm_up_kernel<<<dim3(64, 32), 128, GEMM_SMEM>>>();
    // 3: attention (rope fused, f32x2) — ncu capture slot
    attn_kernel<<<dim3(S_ / TQ, H_, B_), 128, ATTN_SMEM>>>();
    // 4: output projection
    gemm_out_kernel<<<dim3(16, 32), 128, GEMM_SMEM>>>(out);
}

// round 14
// speedup vs baseline: 1.2396x; 1.2396x over previous
#include <cuda_runtime.h>
#include <cstdint>
#include <math.h>
#include <mma.h>

using namespace nvcuda;

// Problem constants
#define B_ 2
#define S_ 2048
#define D_ 2048
#define H_ 16
#define HD_ 128
#define RD_ 64
#define L_ 512
#define QDIM (HD_ + RD_)      // 192
#define KVDIM (2*HD_ + RD_)   // 320
#define MROWS (B_ * S_)       // 4096

// Scratch (device globals; no cudaMalloc allowed)
__device__ float g_ckv[MROWS * L_];
__device__ float g_cq [MROWS * L_];
__device__ float g_kv [MROWS * H_ * KVDIM];
__device__ float g_q  [MROWS * H_ * QDIM];
__device__ float g_ctx[MROWS * H_ * HD_];
// tf32-rounded operand copies
__device__ float g_xt [MROWS * D_];
__device__ float g_w1t[D_ * L_];
__device__ float g_w2t[L_ * H_ * KVDIM];
__device__ float g_w3t[D_ * L_];
__device__ float g_w4t[L_ * H_ * QDIM];
__device__ float g_w5t[H_ * HD_ * D_];
// RoPE tables: [S_][32]
__device__ float g_cost[S_ * 32];
__device__ float g_sint[S_ * 32];

// ----------------------------------------------------------------------------
// Prep kernel: all 6 tf32 conversions + RoPE cos/sin table, one launch.
// ----------------------------------------------------------------------------
__device__ __forceinline__ float4 cvt4(float4 v) {
    v.x = wmma::__float_to_tf32(v.x);
    v.y = wmma::__float_to_tf32(v.y);
    v.z = wmma::__float_to_tf32(v.z);
    v.w = wmma::__float_to_tf32(v.w);
    return v;
}

__global__ void __launch_bounds__(256) prep_kernel(
    const float4* __restrict__ x,  const float4* __restrict__ w1,
    const float4* __restrict__ w2, const float4* __restrict__ w3,
    const float4* __restrict__ w4, const float4* __restrict__ w5)
{
    int idx = blockIdx.x * 256 + threadIdx.x;

    if (idx < S_ * 32) {
        int s = idx >> 5, i = idx & 31;
        const float inv_freq = __expf(-(float)i * (9.210340371976184f / 32.0f));
        const float freq = (float)s * inv_freq;
        g_cost[idx] = cosf(freq);
        g_sint[idx] = sinf(freq);
    }

    if (idx < 2097152) {
        ((float4*)g_xt)[idx] = cvt4(x[idx]);
    } else if (idx < 2359296) {
        int j = idx - 2097152; ((float4*)g_w1t)[j] = cvt4(w1[j]);
    } else if (idx < 3014656) {
        int j = idx - 2359296; ((float4*)g_w2t)[j] = cvt4(w2[j]);
    } else if (idx < 3276800) {
        int j = idx - 3014656; ((float4*)g_w3t)[j] = cvt4(w3[j]);
    } else if (idx < 3670016) {
        int j = idx - 3276800; ((float4*)g_w4t)[j] = cvt4(w4[j]);
    } else if (idx < 4718592) {
        int j = idx - 3670016; ((float4*)g_w5t)[j] = cvt4(w5[j]);
    }
}

// ----------------------------------------------------------------------------
// cp.async helpers
// ----------------------------------------------------------------------------
__device__ __forceinline__ void cp16(float* dst, const float* src) {
    unsigned int s = (unsigned int)__cvta_generic_to_shared(dst);
    asm volatile("cp.async.cg.shared.global [%0], [%1], 16;\n" :: "r"(s), "l"(src));
}
#define CP_COMMIT() asm volatile("cp.async.commit_group;\n" ::: "memory")
#define CP_WAIT1()  asm volatile("cp.async.wait_group 1;\n" ::: "memory")

// ----------------------------------------------------------------------------
// TF32 tensor-core GEMM body (R8-proven), shared by 3 wrapper kernels.
// ----------------------------------------------------------------------------
#define AP 36
#define BP 132
#define STAGES 3
#define A_STG (128 * AP)
#define B_STG (32 * BP)
#define GEMM_SMEM (STAGES * (A_STG + B_STG) * (int)sizeof(float))

__device__ __forceinline__ void tgemm_body(
    const float* __restrict__ A, const float* __restrict__ Bm,
    float* __restrict__ C, int N, int K, int roundC, int bRow, int bCol)
{
    extern __shared__ float sm_g[];
    float* As = sm_g;
    float* Bs = sm_g + STAGES * A_STG;

    const int tid = threadIdx.x;
    const int w   = tid >> 5;
    const int wm  = w & 1;
    const int wn  = w >> 1;

    wmma::fragment<wmma::accumulator, 16, 16, 8, float> c[4][4];
#pragma unroll
    for (int i = 0; i < 4; i++)
#pragma unroll
        for (int j = 0; j < 4; j++) wmma::fill_fragment(c[i][j], 0.f);

    const int ktiles = K >> 5;

    auto load_tile = [&](int buf, int kt) {
        float* as = As + buf * A_STG;
        float* bs = Bs + buf * B_STG;
        const float* Ag = A + (size_t)bRow * K + kt * 32;
        const float* Bg = Bm + (size_t)(kt * 32) * N + bCol;
#pragma unroll
        for (int p = 0; p < 8; p++) {
            int idx = p * 128 + tid;
            int r  = idx >> 3, c4  = idx & 7;
            cp16(&as[r * AP + c4 * 4], Ag + (size_t)r * K + c4 * 4);
            int rb = idx >> 5, cb4 = idx & 31;
            cp16(&bs[rb * BP + cb4 * 4], Bg + (size_t)rb * N + cb4 * 4);
        }
    };

    load_tile(0, 0); CP_COMMIT();
    load_tile(1, 1); CP_COMMIT();

    for (int i = 0; i < ktiles; i++) {
        CP_WAIT1();
        __syncthreads();
        if (i + 2 < ktiles) load_tile((i + 2) % STAGES, i + 2);
        CP_COMMIT();

        const float* as = As + (i % STAGES) * A_STG;
        const float* bs = Bs + (i % STAGES) * B_STG;
#pragma unroll
        for (int ks = 0; ks < 32; ks += 8) {
            wmma::fragment<wmma::matrix_a, 16, 16, 8, wmma::precision::tf32, wmma::row_major> a[4];
            wmma::fragment<wmma::matrix_b, 16, 16, 8, wmma::precision::tf32, wmma::row_major> b[4];
#pragma unroll
            for (int ii = 0; ii < 4; ii++)
                wmma::load_matrix_sync(a[ii], &as[(wm * 64 + ii * 16) * AP + ks], AP);
#pragma unroll
            for (int j = 0; j < 4; j++)
                wmma::load_matrix_sync(b[j], &bs[ks * BP + wn * 64 + j * 16], BP);
#pragma unroll
            for (int ii = 0; ii < 4; ii++)
#pragma unroll
                for (int j = 0; j < 4; j++)
                    wmma::mma_sync(c[ii][j], a[ii], b[j], c[ii][j]);
        }
    }

    if (roundC) {
#pragma unroll
        for (int i = 0; i < 4; i++)
#pragma unroll
            for (int j = 0; j < 4; j++)
#pragma unroll
                for (int t = 0; t < c[i][j].num_elements; t++)
                    c[i][j].x[t] = wmma::__float_to_tf32(c[i][j].x[t]);
    }

#pragma unroll
    for (int i = 0; i < 4; i++)
#pragma unroll
        for (int j = 0; j < 4; j++) {
            size_t row = bRow + wm * 64 + i * 16;
            size_t col = bCol + wn * 64 + j * 16;
            wmma::store_matrix_sync(C + row * N + col, c[i][j], N, wmma::mem_row_major);
        }
}

__global__ void __launch_bounds__(128, 2) gemm_down_kernel()
{
    int bx = blockIdx.x;
    if (bx < 4) tgemm_body(g_xt, g_w1t, g_ckv, L_, D_, 1, blockIdx.y * 128, bx * 128);
    else        tgemm_body(g_xt, g_w3t, g_cq,  L_, D_, 1, blockIdx.y * 128, (bx - 4) * 128);
}

__global__ void __launch_bounds__(128, 2) gemm_up_kernel()
{
    int bx = blockIdx.x;
    if (bx < 40) tgemm_body(g_ckv, g_w2t, g_kv, H_ * KVDIM, L_, 0, blockIdx.y * 128, bx * 128);
    else         tgemm_body(g_cq,  g_w4t, g_q,  H_ * QDIM,  L_, 0, blockIdx.y * 128, (bx - 40) * 128);
}

__global__ void __launch_bounds__(128, 2) gemm_out_kernel(float* __restrict__ out)
{
    tgemm_body(g_ctx, g_w5t, out, D_, D_, 0, blockIdx.y * 128, blockIdx.x * 128);
}

// ----------------------------------------------------------------------------
// Causal flash attention (R8 core: fp32 register-tiled 4x8, serial __expf
// softmax) with fused RoPE and 2-CTA/SM occupancy:
//   - K chunks back to 32 dims (smem 112.9KB -> two CTAs fit in 228KB)
//   - rope chunks (4,5) re-read both halves from gmem (L2-hot)
//   - __launch_bounds__(256,2) pins regs at 128 (2x64K regfile exact fit)
// ----------------------------------------------------------------------------
#define TQ 64
#define TK 64
#define QP 68
#define VP 132
#define SP 68
// sQt 192*QP + sKt 32*QP + sV 64*VP + sS 64*SP + stats 192 = 112,896 B
#define ATTN_SMEM ((192*QP + 32*QP + TK*VP + TQ*SP + 192) * (int)sizeof(float))

__global__ void __launch_bounds__(256, 2) attn_kernel()
{
    extern __shared__ float sm[];
    float* sQt  = sm;                   // [192][QP]  Q^T (roped)
    float* sKt  = sQt + 192 * QP;       // [32][QP]   K^T chunk (roped on the fly)
    float* sV   = sKt + 32 * QP;        // [64][VP]
    float* sS   = sV  + TK * VP;        // [64][SP]
    float* mRow = sS  + TQ * SP;
    float* lRow = mRow + 64;
    float* aRow = lRow + 64;

    const int qt  = blockIdx.x;
    const int h   = blockIdx.y;
    const int b   = blockIdx.z;
    const int qs  = qt * TQ;
    const int tid = threadIdx.x;
    const int ty  = tid >> 4;
    const int tx  = tid & 15;
    const int r0  = ty * 4;

    // Q^T fill, dims 0..127 (no rope)
    for (int idx = tid; idx < TQ * 128; idx += 256) {
        int r = idx >> 7, k = idx & 127;
        sQt[k * QP + r] = g_q[((size_t)(b * S_ + qs + r) * H_ + h) * QDIM + k];
    }
    // Q^T fill, dims 128..191 with RoPE
    for (int idx = tid; idx < TQ * 32; idx += 256) {
        int r = idx >> 5, i = idx & 31;
        size_t base = ((size_t)(b * S_ + qs + r) * H_ + h) * QDIM;
        float x1 = g_q[base + 128 + i];
        float x2 = g_q[base + 160 + i];
        float c  = g_cost[(qs + r) * 32 + i];
        float sn = g_sint[(qs + r) * 32 + i];
        sQt[(128 + i) * QP + r] = x1 * c - x2 * sn;
        sQt[(160 + i) * QP + r] = x2 * c + x1 * sn;
    }
    if (tid < TQ) { mRow[tid] = -INFINITY; lRow[tid] = 0.f; }

    float acc[4][8];
#pragma unroll
    for (int i = 0; i < 4; i++)
#pragma unroll
        for (int j = 0; j < 8; j++) acc[i][j] = 0.f;

    const float scale = 0.07216878364870323f;  // 1/sqrt(192)

    for (int kt = 0; kt <= qt; kt++) {
        const int ks = kt * TK;
        __syncthreads();  // previous iteration done with sS/sV/sKt

        // V tile [64][128] (float4)
        for (int idx4 = tid; idx4 < TK * (HD_ / 4); idx4 += 256) {
            int c = idx4 >> 5, j4 = idx4 & 31;
            float4 v = *(const float4*)(g_kv + ((size_t)(b * S_ + ks + c) * H_ + h) * KVDIM + QDIM + j4 * 4);
            *(float4*)&sV[c * VP + j4 * 4] = v;
        }

        float s[4][4];
#pragma unroll
        for (int i = 0; i < 4; i++)
#pragma unroll
            for (int j = 0; j < 4; j++) s[i][j] = 0.f;

        // 6 chunks of 32 dims; chunks 4,5 apply RoPE on the fly
        for (int dc = 0; dc < 6; dc++) {
            if (dc > 0) __syncthreads();   // protect sKt overwrite
            {
                const int c = tid >> 5;    // 0..7 kcol base
                const int d = tid & 31;    // dim within 32
                if (dc < 4) {
#pragma unroll
                    for (int rr = 0; rr < 8; rr++) {
                        int kc = c + rr * 8;
                        sKt[d * QP + kc] =
                            g_kv[((size_t)(b * S_ + ks + kc) * H_ + h) * KVDIM + dc * 32 + d];
                    }
                } else {
#pragma unroll
                    for (int rr = 0; rr < 8; rr++) {
                        int kc = c + rr * 8;
                        size_t base = ((size_t)(b * S_ + ks + kc) * H_ + h) * KVDIM;
                        float x1 = g_kv[base + 128 + d];
                        float x2 = g_kv[base + 160 + d];
                        float cc = g_cost[(ks + kc) * 32 + d];
                        float sn = g_sint[(ks + kc) * 32 + d];
                        sKt[d * QP + kc] = (dc == 4) ? (x1 * cc - x2 * sn)
                                                     : (x2 * cc + x1 * sn);
                    }
                }
            }
            __syncthreads();
#pragma unroll
            for (int k = 0; k < 32; k++) {
                const int kk = dc * 32 + k;
                float4 qa = *(const float4*)&sQt[kk * QP + r0];
                float4 kb = *(const float4*)&sKt[k  * QP + tx * 4];
                float ra[4] = {qa.x, qa.y, qa.z, qa.w};
                float rb[4] = {kb.x, kb.y, kb.z, kb.w};
#pragma unroll
                for (int i = 0; i < 4; i++)
#pragma unroll
                    for (int j = 0; j < 4; j++)
                        s[i][j] += ra[i] * rb[j];
            }
        }

        // Write scaled+masked scores
        {
            const bool diag = (kt == qt);
#pragma unroll
            for (int i = 0; i < 4; i++) {
                const int gr = qs + r0 + i;
                float4 w;
                float* ws = &w.x;
#pragma unroll
                for (int j = 0; j < 4; j++) {
                    int kc = ks + tx * 4 + j;
                    ws[j] = (diag && kc > gr) ? -1e30f : s[i][j] * scale;
                }
                *(float4*)&sS[(r0 + i) * SP + tx * 4] = w;
            }
        }
        __syncthreads();

        // Online softmax row update (serial per row — proven fastest config)
        if (tid < TQ) {
            const int r = tid;
            float mold = mRow[r];
            float mx = mold;
#pragma unroll
            for (int c = 0; c < TK; c++) mx = fmaxf(mx, sS[r * SP + c]);
            float a = __expf(mold - mx);
            float sum = 0.f;
#pragma unroll
            for (int c = 0; c < TK; c++) {
                float p = __expf(sS[r * SP + c] - mx);
                sS[r * SP + c] = p;
                sum += p;
            }
            lRow[r] = lRow[r] * a + sum;
            mRow[r] = mx;
            aRow[r] = a;
        }
        __syncthreads();

        // acc = acc*alpha + P @ V
        {
            float al[4];
#pragma unroll
            for (int i = 0; i < 4; i++) al[i] = aRow[r0 + i];
#pragma unroll
            for (int i = 0; i < 4; i++)
#pragma unroll
                for (int j = 0; j < 8; j++) acc[i][j] *= al[i];

#pragma unroll 4
            for (int c = 0; c < TK; c++) {
                float4 v0 = *(const float4*)&sV[c * VP + tx * 8];
                float4 v1 = *(const float4*)&sV[c * VP + tx * 8 + 4];
                float p[4];
#pragma unroll
                for (int i = 0; i < 4; i++) p[i] = sS[(r0 + i) * SP + c];
#pragma unroll
                for (int i = 0; i < 4; i++) {
                    acc[i][0] += p[i] * v0.x;
                    acc[i][1] += p[i] * v0.y;
                    acc[i][2] += p[i] * v0.z;
                    acc[i][3] += p[i] * v0.w;
                    acc[i][4] += p[i] * v1.x;
                    acc[i][5] += p[i] * v1.y;
                    acc[i][6] += p[i] * v1.z;
                    acc[i][7] += p[i] * v1.w;
                }
            }
        }
    }

    // Final normalize + store (tf32-rounded: feeds tf32 output GEMM)
#pragma unroll
    for (int i = 0; i < 4; i++) {
        const float invl = 1.0f / lRow[r0 + i];
        size_t ob = ((size_t)(b * S_ + qs + r0 + i) * H_ + h) * HD_ + tx * 8;
        float o[8];
#pragma unroll
        for (int j = 0; j < 8; j++) o[j] = wmma::__float_to_tf32(acc[i][j] * invl);
        *(float4*)(g_ctx + ob)     = make_float4(o[0], o[1], o[2], o[3]);
        *(float4*)(g_ctx + ob + 4) = make_float4(o[4], o[5], o[6], o[7]);
    }
}

// ----------------------------------------------------------------------------
// Launch: 5 kernels; attn at app-launch index 3 (ncu capture slot).
// Inputs (metadata order): x, mask, w_kv_down, w_kv_up, w_q_down, w_q_up, w_o
// ----------------------------------------------------------------------------
extern "C" void kernel_launch(void* const* d_in, const int* in_sizes, int n_in,
                              void* d_out, int out_size)
{
    (void)in_sizes; (void)n_in; (void)out_size;
    const float* x         = (const float*)d_in[0];
    const float* w_kv_down = (const float*)d_in[2];
    const float* w_kv_up   = (const float*)d_in[3];
    const float* w_q_down  = (const float*)d_in[4];
    const float* w_q_up    = (const float*)d_in[5];
    const float* w_o       = (const float*)d_in[6];
    float* out = (float*)d_out;

    cudaFuncSetAttribute(gemm_down_kernel, cudaFuncAttributeMaxDynamicSharedMemorySize, GEMM_SMEM);
    cudaFuncSetAttribute(gemm_up_kernel,   cudaFuncAttributeMaxDynamicSharedMemorySize, GEMM_SMEM);
    cudaFuncSetAttribute(gemm_out_kernel,  cudaFuncAttributeMaxDynamicSharedMemorySize, GEMM_SMEM);
    cudaFuncSetAttribute(attn_kernel,      cudaFuncAttributeMaxDynamicSharedMemorySize, ATTN_SMEM);

    // 0: prep (tf32 conversions + rope tables)
    prep_kernel<<<18432, 256>>>((const float4*)x, (const float4*)w_kv_down,
                                (const float4*)w_kv_up, (const float4*)w_q_down,
                                (const float4*)w_q_up, (const float4*)w_o);
    // 1: fused down projections
    gemm_down_kernel<<<dim3(8, 32), 128, GEMM_SMEM>>>();
    // 2: fused up projections
    gemm_up_kernel<<<dim3(64, 32), 128, GEMM_SMEM>>>();
    // 3: attention (rope fused, 2 CTAs/SM) — ncu capture slot
    attn_kernel<<<dim3(S_ / TQ, H_, B_), 256, ATTN_SMEM>>>();
    // 4: output projection
    gemm_out_kernel<<<dim3(16, 32), 128, GEMM_SMEM>>>(out);
}